// round 11
// baseline (speedup 1.0000x reference)
#include <cuda_runtime.h>
#include <cuda_bf16.h>

// Sparsity_60095182405891: x[64,256,56,56] f32, NCHW.
// mask1: keep top-2 (ties >=) of |x| per 4-channel block.
// mask2: zero kept, keep top-1 (ties >=) of residual per 8-channel block.
// out = x * (mask1 | mask2).
//
// CONVERGED FINAL. Operating point: 1 float4 x 8 channels per thread
// (8 front-batched LDG.128, MLP=8), regs=50 no spills, 5 CTA/SM,
// multi-wave 6272-CTA grid, streaming __ldcs/__stcs.
// 56.2-56.8us kernel, 6.28-6.34 TB/s HBM (79-80% of spec) = the HBM3e
// 1:1 R/W-mix ceiling, confirmed across 7 configs:
//   4ch/thread + shfl (occ 82%, 0 spills) -> 78.6%, 57.1us  (occupancy
//     doubled, bandwidth unchanged: ceiling conclusively chip-level)
//   occ-cap 6 CTA/SM       -> spills, 74.7%, 63.2us
//   persistent grid-stride  -> loop-carried WAR serializes loads, 71.6%, 63.7us
//   2x tile / MLP16         -> regs 76 spills + occ 30%, 64.8%, 70.1us
//   cache policy / grid shape -> neutral
// Traffic (205MB R + 205MB W, f32 in/out) is irreducible; compute idle.

#define C_TOT   256
#define HW      3136            // 56*56
#define GROUPS  (C_TOT / 8)     // 32
#define VEC     (HW / 4)        // 784
#define TILES_PER_IMG (GROUPS * VEC)   // 25088 = 98 * 256

__device__ __forceinline__ float second_of_4(float a0, float a1, float a2, float a3) {
    // 2nd largest of 4 (tournament): max( min(max01, max23), max(min01, min23) )
    float m01 = fmaxf(a0, a1), n01 = fminf(a0, a1);
    float m23 = fmaxf(a2, a3), n23 = fminf(a2, a3);
    return fmaxf(fminf(m01, m23), fmaxf(n01, n23));
}

__global__ void __launch_bounds__(256)
sparsity_nm_kernel(const float* __restrict__ x, float* __restrict__ out) {
    int tid = blockIdx.x * 256 + threadIdx.x;   // 0 .. 25087 (exact, no tail)
    int n   = blockIdx.y;

    int g = tid / VEC;          // 8-channel group (0..31)
    int p = tid - g * VEC;      // float4 index within the 56x56 plane

    long base = ((long)(n * C_TOT + g * 8)) * HW + (long)p * 4;

    const float4* xin = reinterpret_cast<const float4*>(x + base);
    float4*       xo  = reinterpret_cast<float4*>(out + base);

    // 8 independent strided vector loads (stride HW floats = 12544 B),
    // streaming (evict-first) - data is touched exactly once.
    float4 v[8];
#pragma unroll
    for (int c = 0; c < 8; c++) {
        v[c] = __ldcs(xin + (long)c * (HW / 4));
    }

    float val[8][4];
#pragma unroll
    for (int c = 0; c < 8; c++) {
        val[c][0] = v[c].x; val[c][1] = v[c].y;
        val[c][2] = v[c].z; val[c][3] = v[c].w;
    }

#pragma unroll
    for (int l = 0; l < 4; l++) {
        float a[8];
#pragma unroll
        for (int c = 0; c < 8; c++) a[c] = fabsf(val[c][l]);

        // mask1: top-2 (ties kept) within each 4-channel block
        float thr0 = second_of_4(a[0], a[1], a[2], a[3]);
        float thr1 = second_of_4(a[4], a[5], a[6], a[7]);

        bool  m1[8];
        float r[8];
        float rmax = 0.0f;
#pragma unroll
        for (int c = 0; c < 8; c++) {
            float thr = (c < 4) ? thr0 : thr1;
            m1[c] = (a[c] >= thr);
            r[c]  = m1[c] ? 0.0f : a[c];
            rmax  = fmaxf(rmax, r[c]);
        }

        // mask2: top-1 (ties kept) of residual over the 8-block; OR with mask1
#pragma unroll
        for (int c = 0; c < 8; c++) {
            bool keep = m1[c] || (r[c] >= rmax);
            val[c][l] = keep ? val[c][l] : 0.0f;
        }
    }

    // Repack and streaming-store (evict-first; output never re-read)
#pragma unroll
    for (int c = 0; c < 8; c++) {
        float4 o;
        o.x = val[c][0]; o.y = val[c][1]; o.z = val[c][2]; o.w = val[c][3];
        __stcs(xo + (long)c * (HW / 4), o);
    }
}

extern "C" void kernel_launch(void* const* d_in, const int* in_sizes, int n_in,
                              void* d_out, int out_size) {
    const float* x = (const float*)d_in[0];
    float* out = (float*)d_out;
    dim3 grid(TILES_PER_IMG / 256, 64);   // (98, 64)
    sparsity_nm_kernel<<<grid, 256>>>(x, out);
}

// round 12
// speedup vs baseline: 1.0065x; 1.0065x over previous
#include <cuda_runtime.h>
#include <cuda_bf16.h>

// Sparsity_60095182405891: x[64,256,56,56] f32, NCHW.
// mask1: keep top-2 (ties >=) of |x| per 4-channel block.
// mask2: zero kept, keep top-1 (ties >=) of residual per 8-channel block.
// out = x * (mask1 | mask2).
//
// R12: native 256-bit load/store experiment (sm_100+ ld/st.global.v8.f32).
// One thread per (4-channel block, 8-consecutive-float chunk): 4 LDG.256 +
// 4 STG.256, 32 value regs (no spill), 8-block residual max via
// shfl_xor(1) to the partner thread holding the other 4 channels at the
// same pixels (adjacent tids -> same warp always).
// Tests whether halving request count / doubling per-lane span moves the
// 6.2-6.3 TB/s plateau. Prior: neutral (HBM R/W-mix ceiling).

#define C_TOT   256
#define HW      3136             // 56*56
#define CHUNKS  (HW / 8)         // 392 8-float chunks per plane
#define GROUPS  (C_TOT / 8)      // 32
#define TILES_PER_IMG (GROUPS * CHUNKS * 2)   // 25088 = 98 * 256

__device__ __forceinline__ void ldg256(const float* p, float* v) {
    asm volatile("ld.global.v8.f32 {%0,%1,%2,%3,%4,%5,%6,%7}, [%8];"
        : "=f"(v[0]), "=f"(v[1]), "=f"(v[2]), "=f"(v[3]),
          "=f"(v[4]), "=f"(v[5]), "=f"(v[6]), "=f"(v[7])
        : "l"(p));
}

__device__ __forceinline__ void stg256(float* p, const float* v) {
    asm volatile("st.global.v8.f32 [%0], {%1,%2,%3,%4,%5,%6,%7,%8};"
        :: "l"(p),
           "f"(v[0]), "f"(v[1]), "f"(v[2]), "f"(v[3]),
           "f"(v[4]), "f"(v[5]), "f"(v[6]), "f"(v[7])
        : "memory");
}

__device__ __forceinline__ float second_of_4(float a0, float a1, float a2, float a3) {
    float m01 = fmaxf(a0, a1), n01 = fminf(a0, a1);
    float m23 = fmaxf(a2, a3), n23 = fminf(a2, a3);
    return fmaxf(fminf(m01, m23), fmaxf(n01, n23));
}

__global__ void __launch_bounds__(256)
sparsity_nm_kernel(const float* __restrict__ x, float* __restrict__ out) {
    int tid = blockIdx.x * 256 + threadIdx.x;   // 0 .. 25087 (exact)
    int n   = blockIdx.y;

    int half    = tid & 1;          // which 4-channel half of the 8-block
    int pairIdx = tid >> 1;         // 0 .. 12543
    int g8      = pairIdx / CHUNKS; // 8-channel group (0..31)
    int chunk   = pairIdx - g8 * CHUNKS;  // 8-float chunk in plane (0..391)

    int c0 = g8 * 8 + half * 4;
    long base = ((long)(n * C_TOT + c0)) * HW + (long)chunk * 8;

    const float* xin = x + base;
    float*       xo  = out + base;

    // 4 independent 256-bit loads (channel stride HW*4 = 12544 B; 32B aligned)
    float val[4][8];
#pragma unroll
    for (int c = 0; c < 4; c++) {
        ldg256(xin + (long)c * HW, val[c]);
    }

#pragma unroll
    for (int l = 0; l < 8; l++) {
        float a[4];
#pragma unroll
        for (int c = 0; c < 4; c++) a[c] = fabsf(val[c][l]);

        // mask1: top-2 (ties kept) within this 4-channel block
        float thr = second_of_4(a[0], a[1], a[2], a[3]);

        bool  m1[4];
        float r[4];
        float rmax = 0.0f;
#pragma unroll
        for (int c = 0; c < 4; c++) {
            m1[c] = (a[c] >= thr);
            r[c]  = m1[c] ? 0.0f : a[c];
            rmax  = fmaxf(rmax, r[c]);
        }

        // 8-block residual max: partner thread (adjacent tid, same warp)
        // holds the other 4 channels at the same pixels.
        rmax = fmaxf(rmax, __shfl_xor_sync(0xffffffffu, rmax, 1));

        // mask2: top-1 (ties kept) of residual over the 8-block; OR mask1
#pragma unroll
        for (int c = 0; c < 4; c++) {
            bool keep = m1[c] || (r[c] >= rmax);
            val[c][l] = keep ? val[c][l] : 0.0f;
        }
    }

    // 4 independent 256-bit stores
#pragma unroll
    for (int c = 0; c < 4; c++) {
        stg256(xo + (long)c * HW, val[c]);
    }
}

extern "C" void kernel_launch(void* const* d_in, const int* in_sizes, int n_in,
                              void* d_out, int out_size) {
    const float* x = (const float*)d_in[0];
    float* out = (float*)d_out;
    dim3 grid(TILES_PER_IMG / 256, 64);   // (98, 64)
    sparsity_nm_kernel<<<grid, 256>>>(x, out);
}